// round 14
// baseline (speedup 1.0000x reference)
#include <cuda_runtime.h>
#include <cuda_fp16.h>
#include <cuda_bf16.h>

#define N_NODES 50000
#define E_EDGES 1000000
#define DIM     64
#define G_GRAPHS 512
#define O_DIM   16
#define PAD     64          // padded CSR slots per node (Poisson(20): P(deg>=64)~1e-9)
#define HALF_N  25000       // node-range split for agg1/gemm2 pipelining

// Scratch (__device__ globals; no allocation allowed)
__device__ __half g_p [N_NODES * DIM];      // projected (Wl) features, fp16
__device__ float g_xr  [N_NODES * DIM];     // root-path (Wr) features
__device__ float g_h1  [N_NODES * DIM];     // layer-1 output
__device__ float g_pool[G_GRAPHS * DIM];
__device__ int   g_cursor[N_NODES];         // degree counters (padded CSR)
__device__ int   g_esrc  [N_NODES * PAD];   // padded edge lists

#define FMA2(d, a, b) \
    asm("fma.rn.f32x2 %0, %1, %2, %0;" : "+l"(d) : "l"(a), "l"(b))
#define PACK2(d, lo, hi) \
    asm("mov.b64 %0, {%1, %2};" : "=l"(d) : "f"(lo), "f"(hi))
#define UNPACK2(lo, hi, s) \
    asm("mov.b64 {%0, %1}, %2;" : "=f"(lo), "=f"(hi) : "l"(s))

// ---------------------------------------------------------------------------
// zero cursor + pool
// ---------------------------------------------------------------------------
__global__ void zero2_kernel(int* __restrict__ cursor, float* __restrict__ pool) {
    int i = blockIdx.x * blockDim.x + threadIdx.x;
    if (i < N_NODES) cursor[i] = 0;
    if (i < G_GRAPHS * DIM) pool[i] = 0.f;
}

// ---------------------------------------------------------------------------
// padded-CSR place: 1 edge / thread. No hist, no scan.
// ---------------------------------------------------------------------------
__global__ void place_kernel(const int* __restrict__ src, const int* __restrict__ dst,
                             int* __restrict__ cursor, int* __restrict__ esrc) {
    int e = blockIdx.x * blockDim.x + threadIdx.x;
    if (e >= E_EDGES) return;
    int d = __ldg(&dst[e]);
    int p = atomicAdd(&cursor[d], 1);
    if (p < PAD) esrc[(d << 6) + p] = __ldg(&src[e]);
}

// ---------------------------------------------------------------------------
// dual GEMM, f32x2-packed ACROSS the two matrices:
//   lane0 = in @ Wl -> p (fp16),   lane1 = in @ Wr + b -> xr (fp32)
// Operates on node rows [rbeg, rend).
// ---------------------------------------------------------------------------
__global__ __launch_bounds__(256) void dual_gemm_kernel(
        const float* __restrict__ in, const float* __restrict__ Wl,
        const float* __restrict__ Wr, const float* __restrict__ b,
        __half* __restrict__ p, float* __restrict__ xr, int rbeg, int rend) {
    extern __shared__ float sm[];
    unsigned long long* sW2 = (unsigned long long*)sm;   // 32 KB
    float* sIn = (float*)(sW2 + 4096);                   // 128*68 floats
    __shared__ float sB[64];

    int tid = threadIdx.x;

    for (int i = tid; i < 1024; i += 256) {
        float4 wl = __ldg(&((const float4*)Wl)[i]);
        float4 wr = __ldg(&((const float4*)Wr)[i]);
        int base = (i >> 4) * 64 + (i & 15) * 4;
        unsigned long long u0, u1, u2, u3;
        PACK2(u0, wl.x, wr.x);
        PACK2(u1, wl.y, wr.y);
        PACK2(u2, wl.z, wr.z);
        PACK2(u3, wl.w, wr.w);
        sW2[base + 0] = u0;
        sW2[base + 1] = u1;
        sW2[base + 2] = u2;
        sW2[base + 3] = u3;
    }
    if (tid < 64) sB[tid] = __ldg(&b[tid]);

    int row0 = rbeg + blockIdx.x * 128;
    for (int i = tid; i < 2048; i += 256) {
        int r = i >> 4, c4 = i & 15;
        float4 v = make_float4(0.f, 0.f, 0.f, 0.f);
        int gr = row0 + r;
        if (gr < rend) v = __ldg(&((const float4*)in)[gr * 16 + c4]);
        *(float4*)&sIn[r * 68 + c4 * 4] = v;
    }
    __syncthreads();

    int tx = tid & 15, ty = tid >> 4;
    int cg = tx * 4;

    unsigned long long acc[8][4];
    #pragma unroll
    for (int i = 0; i < 8; i++) {
        #pragma unroll
        for (int j = 0; j < 4; j++) PACK2(acc[i][j], 0.f, sB[cg + j]);
    }

    #pragma unroll 8
    for (int k = 0; k < 64; k++) {
        ulonglong2 w01 = *(const ulonglong2*)&sW2[k * 64 + cg];
        ulonglong2 w23 = *(const ulonglong2*)&sW2[k * 64 + cg + 2];
        #pragma unroll
        for (int i = 0; i < 8; i++) {
            float a = sIn[(ty + 16 * i) * 68 + k];
            unsigned long long aa;
            PACK2(aa, a, a);
            FMA2(acc[i][0], aa, w01.x);
            FMA2(acc[i][1], aa, w01.y);
            FMA2(acc[i][2], aa, w23.x);
            FMA2(acc[i][3], aa, w23.y);
        }
    }

    #pragma unroll
    for (int i = 0; i < 8; i++) {
        int gr = row0 + ty + 16 * i;
        if (gr < rend) {
            float l0, r0, l1, r1, l2, r2, l3, r3;
            UNPACK2(l0, r0, acc[i][0]);
            UNPACK2(l1, r1, acc[i][1]);
            UNPACK2(l2, r2, acc[i][2]);
            UNPACK2(l3, r3, acc[i][3]);
            __half2 h01 = __floats2half2_rn(l0, l1);
            __half2 h23 = __floats2half2_rn(l2, l3);
            uint2 hp;
            hp.x = *(unsigned int*)&h01;
            hp.y = *(unsigned int*)&h23;
            *(uint2*)&p[gr * 64 + cg] = hp;
            *(float4*)&xr[gr * 64 + cg] = make_float4(r0, r1, r2, r3);
        }
    }
}

// ---------------------------------------------------------------------------
// agg helpers (inline functions — no macro token-collision hazards)
// ---------------------------------------------------------------------------
struct Acc8 {
    float2 a0, a1, a2, a3;
};

__device__ __forceinline__ void acc_quad(Acc8& A, const uint4& p0, const uint4& p1,
                                         const uint4& p2, const uint4& p3) {
    __half2 q0 = __hadd2(__hadd2(*(const __half2*)&p0.x, *(const __half2*)&p1.x),
                         __hadd2(*(const __half2*)&p2.x, *(const __half2*)&p3.x));
    __half2 q1 = __hadd2(__hadd2(*(const __half2*)&p0.y, *(const __half2*)&p1.y),
                         __hadd2(*(const __half2*)&p2.y, *(const __half2*)&p3.y));
    __half2 q2 = __hadd2(__hadd2(*(const __half2*)&p0.z, *(const __half2*)&p1.z),
                         __hadd2(*(const __half2*)&p2.z, *(const __half2*)&p3.z));
    __half2 q3 = __hadd2(__hadd2(*(const __half2*)&p0.w, *(const __half2*)&p1.w),
                         __hadd2(*(const __half2*)&p2.w, *(const __half2*)&p3.w));
    float2 f0 = __half22float2(q0); A.a0.x += f0.x; A.a0.y += f0.y;
    float2 f1 = __half22float2(q1); A.a1.x += f1.x; A.a1.y += f1.y;
    float2 f2 = __half22float2(q2); A.a2.x += f2.x; A.a2.y += f2.y;
    float2 f3 = __half22float2(q3); A.a3.x += f3.x; A.a3.y += f3.y;
}

__device__ __forceinline__ void acc_one(Acc8& A, const uint4& p0) {
    float2 f0 = __half22float2(*(const __half2*)&p0.x); A.a0.x += f0.x; A.a0.y += f0.y;
    float2 f1 = __half22float2(*(const __half2*)&p0.y); A.a1.x += f1.x; A.a1.y += f1.y;
    float2 f2 = __half22float2(*(const __half2*)&p0.z); A.a2.x += f2.x; A.a2.y += f2.y;
    float2 f3 = __half22float2(*(const __half2*)&p0.w); A.a3.x += f3.x; A.a3.y += f3.y;
}

// ---------------------------------------------------------------------------
// fused aggregation + epilogue (fp16 gather, fp32 accumulate)
// 8 lanes/node; padded CSR. Node range [nbeg, nend).
//   POOL=0:  out[node] = relu( segsum(p) + xr[node] )
//   POOL=1:  pool[batch[node]] += relu( segsum(p) + xr[node] )
// ---------------------------------------------------------------------------
template<int POOL>
__global__ __launch_bounds__(256) void agg_epi_kernel(
        const __half* __restrict__ p,  const float* __restrict__ xr,
        const int* __restrict__ degs, const int* __restrict__ esrc,
        float* __restrict__ out, const int* __restrict__ batch,
        float* __restrict__ pool, int nbeg, int nend) {
    int node = nbeg + ((blockIdx.x * blockDim.x + threadIdx.x) >> 3);
    int lane = threadIdx.x & 7;
    if (node >= nend) return;
    int deg = min(__ldg(&degs[node]), PAD);
    int beg = node << 6;
    int end = beg + deg;

    const uint4* f = (const uint4*)p;    // row = 8 uint4 (64 halves)

    Acc8 A;
    A.a0 = make_float2(0.f, 0.f);
    A.a1 = A.a0; A.a2 = A.a0; A.a3 = A.a0;

    int e = beg;
    for (; e + 7 < end; e += 8) {
        int s0 = __ldg(&esrc[e]);
        int s1 = __ldg(&esrc[e + 1]);
        int s2 = __ldg(&esrc[e + 2]);
        int s3 = __ldg(&esrc[e + 3]);
        int s4 = __ldg(&esrc[e + 4]);
        int s5 = __ldg(&esrc[e + 5]);
        int s6 = __ldg(&esrc[e + 6]);
        int s7 = __ldg(&esrc[e + 7]);
        uint4 v0 = __ldg(&f[s0 * 8 + lane]);
        uint4 v1 = __ldg(&f[s1 * 8 + lane]);
        uint4 v2 = __ldg(&f[s2 * 8 + lane]);
        uint4 v3 = __ldg(&f[s3 * 8 + lane]);
        uint4 v4 = __ldg(&f[s4 * 8 + lane]);
        uint4 v5 = __ldg(&f[s5 * 8 + lane]);
        uint4 v6 = __ldg(&f[s6 * 8 + lane]);
        uint4 v7 = __ldg(&f[s7 * 8 + lane]);
        acc_quad(A, v0, v1, v2, v3);
        acc_quad(A, v4, v5, v6, v7);
    }
    if (e + 3 < end) {
        int s0 = __ldg(&esrc[e]);
        int s1 = __ldg(&esrc[e + 1]);
        int s2 = __ldg(&esrc[e + 2]);
        int s3 = __ldg(&esrc[e + 3]);
        uint4 v0 = __ldg(&f[s0 * 8 + lane]);
        uint4 v1 = __ldg(&f[s1 * 8 + lane]);
        uint4 v2 = __ldg(&f[s2 * 8 + lane]);
        uint4 v3 = __ldg(&f[s3 * 8 + lane]);
        acc_quad(A, v0, v1, v2, v3);
        e += 4;
    }
    for (; e < end; e++) {
        int s0 = __ldg(&esrc[e]);
        uint4 v0 = __ldg(&f[s0 * 8 + lane]);
        acc_one(A, v0);
    }

    const float4* xr4 = (const float4*)xr;
    float4 r0 = __ldg(&xr4[node * 16 + lane * 2]);
    float4 r1 = __ldg(&xr4[node * 16 + lane * 2 + 1]);
    float4 o0, o1;
    o0.x = fmaxf(A.a0.x + r0.x, 0.f);
    o0.y = fmaxf(A.a0.y + r0.y, 0.f);
    o0.z = fmaxf(A.a1.x + r0.z, 0.f);
    o0.w = fmaxf(A.a1.y + r0.w, 0.f);
    o1.x = fmaxf(A.a2.x + r1.x, 0.f);
    o1.y = fmaxf(A.a2.y + r1.y, 0.f);
    o1.z = fmaxf(A.a3.x + r1.z, 0.f);
    o1.w = fmaxf(A.a3.y + r1.w, 0.f);

    if (POOL) {
        int bg = __ldg(&batch[node]);
        float* pp = &pool[bg * 64 + lane * 8];
        asm volatile("red.global.add.v4.f32 [%0], {%1,%2,%3,%4};"
                     :: "l"(pp), "f"(o0.x), "f"(o0.y), "f"(o0.z), "f"(o0.w) : "memory");
        asm volatile("red.global.add.v4.f32 [%0], {%1,%2,%3,%4};"
                     :: "l"(pp + 4), "f"(o1.x), "f"(o1.y), "f"(o1.z), "f"(o1.w) : "memory");
    } else {
        float4* op = (float4*)&out[node * 64 + lane * 8];
        op[0] = o0;
        op[1] = o1;
    }
}

// ---------------------------------------------------------------------------
// head:  out = pool @ Wo + bo
// ---------------------------------------------------------------------------
__global__ void head_kernel(const float* __restrict__ pool,
                            const float* __restrict__ Wo,
                            const float* __restrict__ bo,
                            float*       __restrict__ out) {
    __shared__ float sW[64 * 16];
    __shared__ float sb[16];
    int tid = threadIdx.x;
    for (int i = tid; i < 64 * 16; i += 256) sW[i] = __ldg(&Wo[i]);
    if (tid < 16) sb[tid] = __ldg(&bo[tid]);
    __syncthreads();

    int t = blockIdx.x * blockDim.x + tid;
    if (t >= G_GRAPHS * O_DIM) return;
    int row = t >> 4;
    int col = t & 15;
    float acc = sb[col];
    const float* pr = &pool[row * 64];
    #pragma unroll
    for (int k = 0; k < 64; k++) acc += pr[k] * sW[k * 16 + col];
    out[row * O_DIM + col] = acc;
}

// ---------------------------------------------------------------------------
// launch
// ---------------------------------------------------------------------------
extern "C" void kernel_launch(void* const* d_in, const int* in_sizes, int n_in,
                              void* d_out, int out_size) {
    const float* x   = (const float*)d_in[0];
    const int*   ei  = (const int*)  d_in[1];
    const int*   bat = (const int*)  d_in[2];
    const float* Wl1 = (const float*)d_in[3];
    const float* Wr1 = (const float*)d_in[4];
    const float* b1  = (const float*)d_in[5];
    const float* Wl2 = (const float*)d_in[6];
    const float* Wr2 = (const float*)d_in[7];
    const float* b2  = (const float*)d_in[8];
    const float* Wo  = (const float*)d_in[9];
    const float* bo  = (const float*)d_in[10];
    float* out = (float*)d_out;

    const int* src = ei;
    const int* dst = ei + E_EDGES;

    __half* p;
    float *xr, *h1, *pool;
    int *cursor, *esrc;
    cudaGetSymbolAddress((void**)&p,      g_p);
    cudaGetSymbolAddress((void**)&xr,     g_xr);
    cudaGetSymbolAddress((void**)&h1,     g_h1);
    cudaGetSymbolAddress((void**)&pool,   g_pool);
    cudaGetSymbolAddress((void**)&cursor, g_cursor);
    cudaGetSymbolAddress((void**)&esrc,   g_esrc);

    static cudaStream_t s1 = nullptr;
    static cudaEvent_t evF = nullptr, evJ = nullptr, evA0 = nullptr,
                       evA1 = nullptr, evG = nullptr;
    static bool attr_done = false;
    const int gemmSmem = 32768 + 128 * 68 * 4;   // 67,584 B
    if (!attr_done) {
        cudaFuncSetAttribute(dual_gemm_kernel,
                             cudaFuncAttributeMaxDynamicSharedMemorySize, gemmSmem);
        cudaStreamCreateWithFlags(&s1, cudaStreamNonBlocking);
        cudaEventCreateWithFlags(&evF, cudaEventDisableTiming);
        cudaEventCreateWithFlags(&evJ, cudaEventDisableTiming);
        cudaEventCreateWithFlags(&evA0, cudaEventDisableTiming);
        cudaEventCreateWithFlags(&evA1, cudaEventDisableTiming);
        cudaEventCreateWithFlags(&evG, cudaEventDisableTiming);
        attr_done = true;
    }

    const int eBlocks    = (E_EDGES + 255) / 256;          // 3907
    const int aggBlocksH = (HALF_N * 8 + 255) / 256;       // 782 (per half)
    const int aggBlocks  = (N_NODES * 8 + 255) / 256;      // 1563
    const int gemmBlocks  = (N_NODES + 127) / 128;         // 391
    const int gemmBlocksH = (HALF_N + 127) / 128;          // 196

    // fork: GEMM-1 (no graph dependency) runs concurrently with CSR build
    cudaEventRecord(evF, 0);
    cudaStreamWaitEvent(s1, evF, 0);

    // stream 0: padded-CSR build
    zero2_kernel<<<(N_NODES + 255) / 256, 256>>>(cursor, pool);
    place_kernel<<<eBlocks, 256>>>(src, dst, cursor, esrc);

    // stream 1: layer-1 projections (full range)
    dual_gemm_kernel<<<gemmBlocks, 256, gemmSmem, s1>>>(x, Wl1, Wr1, b1,
                                                        p, xr, 0, N_NODES);
    cudaEventRecord(evJ, s1);
    cudaStreamWaitEvent(0, evJ, 0);

    // pipelined layer boundary:
    //   s0: agg1 half0 -> agg1 half1
    //   s1: gemm2 half0 (after agg1 half0) -> gemm2 half1 (after agg1 half1)
    agg_epi_kernel<0><<<aggBlocksH, 256>>>(p, xr, cursor, esrc, h1,
                                           nullptr, nullptr, 0, HALF_N);
    cudaEventRecord(evA0, 0);
    agg_epi_kernel<0><<<aggBlocksH, 256>>>(p, xr, cursor, esrc, h1,
                                           nullptr, nullptr, HALF_N, N_NODES);
    cudaEventRecord(evA1, 0);

    cudaStreamWaitEvent(s1, evA0, 0);
    dual_gemm_kernel<<<gemmBlocksH, 256, gemmSmem, s1>>>(h1, Wl2, Wr2, b2,
                                                         p, xr, 0, HALF_N);
    cudaStreamWaitEvent(s1, evA1, 0);
    dual_gemm_kernel<<<gemmBlocksH, 256, gemmSmem, s1>>>(h1, Wl2, Wr2, b2,
                                                         p, xr, HALF_N, N_NODES);
    cudaEventRecord(evG, s1);
    cudaStreamWaitEvent(0, evG, 0);

    // layer-2 aggregation + fused global add pool (full range)
    agg_epi_kernel<1><<<aggBlocks, 256>>>(p, xr, cursor, esrc, nullptr,
                                          bat, pool, 0, N_NODES);

    // head
    head_kernel<<<(G_GRAPHS * O_DIM + 255) / 256, 256>>>(pool, Wo, bo, out);
}

// round 15
// speedup vs baseline: 1.1989x; 1.1989x over previous
#include <cuda_runtime.h>
#include <cuda_fp16.h>
#include <cuda_bf16.h>

#define N_NODES 50000
#define E_EDGES 1000000
#define DIM     64
#define G_GRAPHS 512
#define O_DIM   16
#define PAD     64          // padded CSR slots per node (Poisson(20): P(deg>=64)~1e-9)

// Scratch (__device__ globals; no allocation allowed)
// g_p has ONE EXTRA ROW (index N_NODES): the all-zero sentinel row.
__device__ __half g_p [(N_NODES + 1) * DIM]; // projected (Wl) features, fp16
__device__ float g_xr  [N_NODES * DIM];      // root-path (Wr) features
__device__ float g_h1  [N_NODES * DIM];      // layer-1 output
__device__ float g_pool[G_GRAPHS * DIM];
__device__ int   g_cursor[N_NODES];          // degree counters (padded CSR)
__device__ int   g_esrc  [N_NODES * PAD];    // padded edge lists (sentinel-filled)

#define FMA2(d, a, b) \
    asm("fma.rn.f32x2 %0, %1, %2, %0;" : "+l"(d) : "l"(a), "l"(b))
#define PACK2(d, lo, hi) \
    asm("mov.b64 %0, {%1, %2};" : "=l"(d) : "f"(lo), "f"(hi))
#define UNPACK2(lo, hi, s) \
    asm("mov.b64 {%0, %1}, %2;" : "=f"(lo), "=f"(hi) : "l"(s))

// ---------------------------------------------------------------------------
// init: sentinel-fill esrc, zero cursor/pool, zero p's sentinel row
// grid covers N_NODES*PAD/4 int4 stores (800000 threads)
// ---------------------------------------------------------------------------
__global__ void init_kernel(int* __restrict__ cursor, float* __restrict__ pool,
                            int4* __restrict__ esrc4, __half* __restrict__ p) {
    int i = blockIdx.x * blockDim.x + threadIdx.x;
    int nslots4 = N_NODES * PAD / 4;              // 800000
    if (i < nslots4) esrc4[i] = make_int4(N_NODES, N_NODES, N_NODES, N_NODES);
    if (i < N_NODES) cursor[i] = 0;
    if (i < G_GRAPHS * DIM) pool[i] = 0.f;
    if (i < DIM / 8) {                            // zero sentinel row of p
        ((uint4*)&p[N_NODES * DIM])[i] = make_uint4(0u, 0u, 0u, 0u);
    }
}

// ---------------------------------------------------------------------------
// padded-CSR place: 1 edge / thread. No hist, no scan.
// ---------------------------------------------------------------------------
__global__ void place_kernel(const int* __restrict__ src, const int* __restrict__ dst,
                             int* __restrict__ cursor, int* __restrict__ esrc) {
    int e = blockIdx.x * blockDim.x + threadIdx.x;
    if (e >= E_EDGES) return;
    int d = __ldg(&dst[e]);
    int p = atomicAdd(&cursor[d], 1);
    if (p < PAD) esrc[(d << 6) + p] = __ldg(&src[e]);
}

// ---------------------------------------------------------------------------
// dual GEMM, f32x2-packed ACROSS the two matrices:
//   lane0 = in @ Wl -> p (fp16),   lane1 = in @ Wr + b -> xr (fp32)
// ---------------------------------------------------------------------------
__global__ __launch_bounds__(256) void dual_gemm_kernel(
        const float* __restrict__ in, const float* __restrict__ Wl,
        const float* __restrict__ Wr, const float* __restrict__ b,
        __half* __restrict__ p, float* __restrict__ xr, int n) {
    extern __shared__ float sm[];
    unsigned long long* sW2 = (unsigned long long*)sm;   // 32 KB
    float* sIn = (float*)(sW2 + 4096);                   // 128*68 floats
    __shared__ float sB[64];

    int tid = threadIdx.x;

    for (int i = tid; i < 1024; i += 256) {
        float4 wl = __ldg(&((const float4*)Wl)[i]);
        float4 wr = __ldg(&((const float4*)Wr)[i]);
        int base = (i >> 4) * 64 + (i & 15) * 4;
        unsigned long long u0, u1, u2, u3;
        PACK2(u0, wl.x, wr.x);
        PACK2(u1, wl.y, wr.y);
        PACK2(u2, wl.z, wr.z);
        PACK2(u3, wl.w, wr.w);
        sW2[base + 0] = u0;
        sW2[base + 1] = u1;
        sW2[base + 2] = u2;
        sW2[base + 3] = u3;
    }
    if (tid < 64) sB[tid] = __ldg(&b[tid]);

    int row0 = blockIdx.x * 128;
    for (int i = tid; i < 2048; i += 256) {
        int r = i >> 4, c4 = i & 15;
        float4 v = make_float4(0.f, 0.f, 0.f, 0.f);
        int gr = row0 + r;
        if (gr < n) v = __ldg(&((const float4*)in)[gr * 16 + c4]);
        *(float4*)&sIn[r * 68 + c4 * 4] = v;
    }
    __syncthreads();

    int tx = tid & 15, ty = tid >> 4;
    int cg = tx * 4;

    unsigned long long acc[8][4];
    #pragma unroll
    for (int i = 0; i < 8; i++) {
        #pragma unroll
        for (int j = 0; j < 4; j++) PACK2(acc[i][j], 0.f, sB[cg + j]);
    }

    #pragma unroll 8
    for (int k = 0; k < 64; k++) {
        ulonglong2 w01 = *(const ulonglong2*)&sW2[k * 64 + cg];
        ulonglong2 w23 = *(const ulonglong2*)&sW2[k * 64 + cg + 2];
        #pragma unroll
        for (int i = 0; i < 8; i++) {
            float a = sIn[(ty + 16 * i) * 68 + k];
            unsigned long long aa;
            PACK2(aa, a, a);
            FMA2(acc[i][0], aa, w01.x);
            FMA2(acc[i][1], aa, w01.y);
            FMA2(acc[i][2], aa, w23.x);
            FMA2(acc[i][3], aa, w23.y);
        }
    }

    #pragma unroll
    for (int i = 0; i < 8; i++) {
        int gr = row0 + ty + 16 * i;
        if (gr < n) {
            float l0, r0, l1, r1, l2, r2, l3, r3;
            UNPACK2(l0, r0, acc[i][0]);
            UNPACK2(l1, r1, acc[i][1]);
            UNPACK2(l2, r2, acc[i][2]);
            UNPACK2(l3, r3, acc[i][3]);
            __half2 h01 = __floats2half2_rn(l0, l1);
            __half2 h23 = __floats2half2_rn(l2, l3);
            uint2 hp;
            hp.x = *(unsigned int*)&h01;
            hp.y = *(unsigned int*)&h23;
            *(uint2*)&p[gr * 64 + cg] = hp;
            *(float4*)&xr[gr * 64 + cg] = make_float4(r0, r1, r2, r3);
        }
    }
}

// ---------------------------------------------------------------------------
// agg helpers
// ---------------------------------------------------------------------------
struct Acc8 {
    float2 a0, a1, a2, a3;
};

__device__ __forceinline__ void acc_quad(Acc8& A, const uint4& p0, const uint4& p1,
                                         const uint4& p2, const uint4& p3) {
    __half2 q0 = __hadd2(__hadd2(*(const __half2*)&p0.x, *(const __half2*)&p1.x),
                         __hadd2(*(const __half2*)&p2.x, *(const __half2*)&p3.x));
    __half2 q1 = __hadd2(__hadd2(*(const __half2*)&p0.y, *(const __half2*)&p1.y),
                         __hadd2(*(const __half2*)&p2.y, *(const __half2*)&p3.y));
    __half2 q2 = __hadd2(__hadd2(*(const __half2*)&p0.z, *(const __half2*)&p1.z),
                         __hadd2(*(const __half2*)&p2.z, *(const __half2*)&p3.z));
    __half2 q3 = __hadd2(__hadd2(*(const __half2*)&p0.w, *(const __half2*)&p1.w),
                         __hadd2(*(const __half2*)&p2.w, *(const __half2*)&p3.w));
    float2 f0 = __half22float2(q0); A.a0.x += f0.x; A.a0.y += f0.y;
    float2 f1 = __half22float2(q1); A.a1.x += f1.x; A.a1.y += f1.y;
    float2 f2 = __half22float2(q2); A.a2.x += f2.x; A.a2.y += f2.y;
    float2 f3 = __half22float2(q3); A.a3.x += f3.x; A.a3.y += f3.y;
}

// ---------------------------------------------------------------------------
// fused aggregation + epilogue (fp16 gather, fp32 accumulate)
// 8 lanes/node; sentinel-padded CSR: degree rounded UP to a multiple of 8,
// extra slots hold sentinel index N_NODES -> zero row. NO scalar tail,
// NO branches in the gather loop.
//   POOL=0:  out[node] = relu( segsum(p) + xr[node] )
//   POOL=1:  pool[batch[node]] += relu( segsum(p) + xr[node] )
// ---------------------------------------------------------------------------
template<int POOL>
__global__ __launch_bounds__(256) void agg_epi_kernel(
        const __half* __restrict__ p,  const float* __restrict__ xr,
        const int* __restrict__ degs, const int* __restrict__ esrc,
        float* __restrict__ out, const int* __restrict__ batch,
        float* __restrict__ pool) {
    int node = (blockIdx.x * blockDim.x + threadIdx.x) >> 3;
    int lane = threadIdx.x & 7;
    if (node >= N_NODES) return;
    int deg = min(__ldg(&degs[node]), PAD);
    int degr = (deg + 7) & ~7;          // round up to multiple of 8 (<= PAD)
    int beg = node << 6;
    int end = beg + degr;

    const uint4* f = (const uint4*)p;    // row = 8 uint4 (64 halves)

    Acc8 A;
    A.a0 = make_float2(0.f, 0.f);
    A.a1 = A.a0; A.a2 = A.a0; A.a3 = A.a0;

    for (int e = beg; e < end; e += 8) {
        int s0 = __ldg(&esrc[e]);
        int s1 = __ldg(&esrc[e + 1]);
        int s2 = __ldg(&esrc[e + 2]);
        int s3 = __ldg(&esrc[e + 3]);
        int s4 = __ldg(&esrc[e + 4]);
        int s5 = __ldg(&esrc[e + 5]);
        int s6 = __ldg(&esrc[e + 6]);
        int s7 = __ldg(&esrc[e + 7]);
        uint4 v0 = __ldg(&f[s0 * 8 + lane]);
        uint4 v1 = __ldg(&f[s1 * 8 + lane]);
        uint4 v2 = __ldg(&f[s2 * 8 + lane]);
        uint4 v3 = __ldg(&f[s3 * 8 + lane]);
        uint4 v4 = __ldg(&f[s4 * 8 + lane]);
        uint4 v5 = __ldg(&f[s5 * 8 + lane]);
        uint4 v6 = __ldg(&f[s6 * 8 + lane]);
        uint4 v7 = __ldg(&f[s7 * 8 + lane]);
        acc_quad(A, v0, v1, v2, v3);
        acc_quad(A, v4, v5, v6, v7);
    }

    // epilogue: 8 output cols = lane*8 .. lane*8+7
    const float4* xr4 = (const float4*)xr;
    float4 r0 = __ldg(&xr4[node * 16 + lane * 2]);
    float4 r1 = __ldg(&xr4[node * 16 + lane * 2 + 1]);
    float4 o0, o1;
    o0.x = fmaxf(A.a0.x + r0.x, 0.f);
    o0.y = fmaxf(A.a0.y + r0.y, 0.f);
    o0.z = fmaxf(A.a1.x + r0.z, 0.f);
    o0.w = fmaxf(A.a1.y + r0.w, 0.f);
    o1.x = fmaxf(A.a2.x + r1.x, 0.f);
    o1.y = fmaxf(A.a2.y + r1.y, 0.f);
    o1.z = fmaxf(A.a3.x + r1.z, 0.f);
    o1.w = fmaxf(A.a3.y + r1.w, 0.f);

    if (POOL) {
        int bg = __ldg(&batch[node]);
        float* pp = &pool[bg * 64 + lane * 8];
        asm volatile("red.global.add.v4.f32 [%0], {%1,%2,%3,%4};"
                     :: "l"(pp), "f"(o0.x), "f"(o0.y), "f"(o0.z), "f"(o0.w) : "memory");
        asm volatile("red.global.add.v4.f32 [%0], {%1,%2,%3,%4};"
                     :: "l"(pp + 4), "f"(o1.x), "f"(o1.y), "f"(o1.z), "f"(o1.w) : "memory");
    } else {
        float4* op = (float4*)&out[node * 64 + lane * 8];
        op[0] = o0;
        op[1] = o1;
    }
}

// ---------------------------------------------------------------------------
// head:  out = pool @ Wo + bo
// ---------------------------------------------------------------------------
__global__ void head_kernel(const float* __restrict__ pool,
                            const float* __restrict__ Wo,
                            const float* __restrict__ bo,
                            float*       __restrict__ out) {
    __shared__ float sW[64 * 16];
    __shared__ float sb[16];
    int tid = threadIdx.x;
    for (int i = tid; i < 64 * 16; i += 256) sW[i] = __ldg(&Wo[i]);
    if (tid < 16) sb[tid] = __ldg(&bo[tid]);
    __syncthreads();

    int t = blockIdx.x * blockDim.x + tid;
    if (t >= G_GRAPHS * O_DIM) return;
    int row = t >> 4;
    int col = t & 15;
    float acc = sb[col];
    const float* pr = &pool[row * 64];
    #pragma unroll
    for (int k = 0; k < 64; k++) acc += pr[k] * sW[k * 16 + col];
    out[row * O_DIM + col] = acc;
}

// ---------------------------------------------------------------------------
// launch
// ---------------------------------------------------------------------------
extern "C" void kernel_launch(void* const* d_in, const int* in_sizes, int n_in,
                              void* d_out, int out_size) {
    const float* x   = (const float*)d_in[0];
    const int*   ei  = (const int*)  d_in[1];
    const int*   bat = (const int*)  d_in[2];
    const float* Wl1 = (const float*)d_in[3];
    const float* Wr1 = (const float*)d_in[4];
    const float* b1  = (const float*)d_in[5];
    const float* Wl2 = (const float*)d_in[6];
    const float* Wr2 = (const float*)d_in[7];
    const float* b2  = (const float*)d_in[8];
    const float* Wo  = (const float*)d_in[9];
    const float* bo  = (const float*)d_in[10];
    float* out = (float*)d_out;

    const int* src = ei;
    const int* dst = ei + E_EDGES;

    __half* p;
    float *xr, *h1, *pool;
    int *cursor, *esrc;
    cudaGetSymbolAddress((void**)&p,      g_p);
    cudaGetSymbolAddress((void**)&xr,     g_xr);
    cudaGetSymbolAddress((void**)&h1,     g_h1);
    cudaGetSymbolAddress((void**)&pool,   g_pool);
    cudaGetSymbolAddress((void**)&cursor, g_cursor);
    cudaGetSymbolAddress((void**)&esrc,   g_esrc);

    static cudaStream_t s1 = nullptr;
    static cudaEvent_t evF = nullptr, evJ = nullptr;
    static bool attr_done = false;
    const int gemmSmem = 32768 + 128 * 68 * 4;   // 67,584 B
    if (!attr_done) {
        cudaFuncSetAttribute(dual_gemm_kernel,
                             cudaFuncAttributeMaxDynamicSharedMemorySize, gemmSmem);
        cudaStreamCreateWithFlags(&s1, cudaStreamNonBlocking);
        cudaEventCreateWithFlags(&evF, cudaEventDisableTiming);
        cudaEventCreateWithFlags(&evJ, cudaEventDisableTiming);
        attr_done = true;
    }

    const int initBlocks = (N_NODES * PAD / 4 + 255) / 256;  // 3125
    const int eBlocks    = (E_EDGES + 255) / 256;            // 3907
    const int aggBlocks  = (N_NODES * 8 + 255) / 256;        // 1563
    const int gemmBlocks = (N_NODES + 127) / 128;            // 391

    // fork: GEMM-1 (no graph dependency) runs concurrently with CSR build
    cudaEventRecord(evF, 0);
    cudaStreamWaitEvent(s1, evF, 0);

    // stream 0: sentinel-fill + padded-CSR build
    init_kernel<<<initBlocks, 256>>>(cursor, pool, (int4*)esrc, p);
    place_kernel<<<eBlocks, 256>>>(src, dst, cursor, esrc);

    // stream 1: layer-1 projections  p = x@Wl1 (fp16), xr = x@Wr1 + b1
    dual_gemm_kernel<<<gemmBlocks, 256, gemmSmem, s1>>>(x, Wl1, Wr1, b1, p, xr, N_NODES);
    cudaEventRecord(evJ, s1);
    cudaStreamWaitEvent(0, evJ, 0);

    // layer 1 aggregate + epilogue -> h1
    agg_epi_kernel<0><<<aggBlocks, 256>>>(p, xr, cursor, esrc, h1, nullptr, nullptr);

    // layer 2 projections + aggregate (+ fused global add pool)
    dual_gemm_kernel<<<gemmBlocks, 256, gemmSmem>>>(h1, Wl2, Wr2, b2, p, xr, N_NODES);
    agg_epi_kernel<1><<<aggBlocks, 256>>>(p, xr, cursor, esrc, nullptr, bat, pool);

    // head
    head_kernel<<<(G_GRAPHS * O_DIM + 255) / 256, 256>>>(pool, Wo, bo, out);
}